// round 1
// baseline (speedup 1.0000x reference)
#include <cuda_runtime.h>
#include <math.h>

#define B_N 32768
#define D_N 512
#define K_N 1024
#define L_N 4
#define BM  32
#define TBL 256

#define SMEM_BYTES ((BM*D_N + BM*K_N + 16*256) * sizeof(float))  // 212,992 B

// Scratch (allocation-free rules: __device__ globals)
__device__ float g_zr[(size_t)B_N * D_N];   // residual z, 64 MB
__device__ float g_csq[L_N * K_N];          // per-level ||c||^2

// ---------------------------------------------------------------------------
// c_sq precompute: one warp per codebook row
// ---------------------------------------------------------------------------
__global__ void csq_kernel(const float* __restrict__ cb)
{
    int warp = (blockIdx.x * blockDim.x + threadIdx.x) >> 5;
    int lane = threadIdx.x & 31;
    if (warp >= L_N * K_N) return;
    const float* row = cb + (size_t)warp * D_N;
    float s = 0.f;
    #pragma unroll 4
    for (int i = lane; i < D_N; i += 32) { float v = row[i]; s += v * v; }
    #pragma unroll
    for (int o = 16; o; o >>= 1) s += __shfl_xor_sync(0xffffffffu, s, o);
    if (lane == 0) g_csq[warp] = s;
}

// ---------------------------------------------------------------------------
// Whitening: g_zr = z0 @ W^T   (M=32768, N=512, Kr=512; NT layout)
// CTA tile 64x64, threads 16x16, thread tile 4x4
// ---------------------------------------------------------------------------
__global__ __launch_bounds__(256)
void whiten_kernel(const float* __restrict__ z0, const float* __restrict__ W)
{
    __shared__ float As[16][68];
    __shared__ float Bs[16][68];
    int tid = threadIdx.x;
    int tx = tid & 15, ty = tid >> 4;
    int mb = blockIdx.y * 64, nb = blockIdx.x * 64;
    int lr = tid >> 2;            // 0..63: tile row
    int lk = (tid & 3) << 2;      // 0,4,8,12: k offset

    float acc[4][4];
    #pragma unroll
    for (int i = 0; i < 4; i++)
        #pragma unroll
        for (int j = 0; j < 4; j++) acc[i][j] = 0.f;

    for (int k0 = 0; k0 < D_N; k0 += 16) {
        float4 av = *(const float4*)&z0[(size_t)(mb + lr) * D_N + k0 + lk];
        float4 bv = *(const float4*)&W [(size_t)(nb + lr) * D_N + k0 + lk];
        __syncthreads();
        As[lk+0][lr] = av.x; As[lk+1][lr] = av.y; As[lk+2][lr] = av.z; As[lk+3][lr] = av.w;
        Bs[lk+0][lr] = bv.x; Bs[lk+1][lr] = bv.y; Bs[lk+2][lr] = bv.z; Bs[lk+3][lr] = bv.w;
        __syncthreads();
        #pragma unroll
        for (int k = 0; k < 16; k++) {
            float4 a = *(const float4*)&As[k][ty << 2];
            float4 b = *(const float4*)&Bs[k][tx << 2];
            float aa[4] = {a.x, a.y, a.z, a.w};
            float bb[4] = {b.x, b.y, b.z, b.w};
            #pragma unroll
            for (int i = 0; i < 4; i++)
                #pragma unroll
                for (int j = 0; j < 4; j++) acc[i][j] = fmaf(aa[i], bb[j], acc[i][j]);
        }
    }
    #pragma unroll
    for (int i = 0; i < 4; i++) {
        float4 o = make_float4(acc[i][0], acc[i][1], acc[i][2], acc[i][3]);
        *(float4*)&g_zr[(size_t)(mb + (ty << 2) + i) * D_N + nb + (tx << 2)] = o;
    }
}

// ---------------------------------------------------------------------------
// Fused level kernel: per CTA = 32 rows.
//   Stage A: S = z_resid @ cb^T          (M=32, N=1024, Kr=512)
//   Softmax: p = softmax((2S - c_sq)/tau), write p, keep p in smem
//   Stage B: z_soft = p @ cb             (M=32, N=512, Kr=1024)
//            write z_soft; g_zr -= z_soft
// ---------------------------------------------------------------------------
__global__ __launch_bounds__(TBL, 1)
void level_kernel(const float* __restrict__ cb, int level,
                  const float* __restrict__ tau,
                  float* __restrict__ out_z, float* __restrict__ out_p)
{
    extern __shared__ float sm[];
    float* zs  = sm;                  // [BM][D_N]  64 KB
    float* S   = sm + BM * D_N;       // [BM][K_N] 128 KB
    float* cbs = S + BM * K_N;        // [16][256]  16 KB (also holds csq)

    const float* csq = g_csq + level * K_N;
    int tid = threadIdx.x;
    int bm0 = blockIdx.x * BM;
    int tx = tid & 31;                // 32 n-threads
    int ty = tid >> 5;                // 8 warps -> m
    int m0 = ty * 4;
    float inv_tau = 1.0f / tau[0];

    // ---- load z tile (coalesced, conflict-free) ----
    #pragma unroll
    for (int i = 0; i < 16; i++) {
        int s = tid + i * TBL;        // 0..4095 float4 slots
        int m = s >> 7;
        int d = (s & 127) << 2;
        *(float4*)&zs[m * D_N + d] = *(const float4*)&g_zr[(size_t)(bm0 + m) * D_N + d];
    }
    __syncthreads();

    // ============================ Stage A ============================
    for (int nb = 0; nb < K_N; nb += 256) {
        float acc[4][8];
        #pragma unroll
        for (int i = 0; i < 4; i++)
            #pragma unroll
            for (int j = 0; j < 8; j++) acc[i][j] = 0.f;

        for (int k0 = 0; k0 < D_N; k0 += 16) {
            float4 t[4];
            #pragma unroll
            for (int i = 0; i < 4; i++) {
                int s  = tid + i * TBL;      // 0..1023
                int n  = s >> 2;             // 0..255
                int kq = (s & 3) << 2;       // 0,4,8,12
                t[i] = *(const float4*)&cb[(size_t)(nb + n) * D_N + k0 + kq];
            }
            __syncthreads();
            #pragma unroll
            for (int i = 0; i < 4; i++) {
                int s  = tid + i * TBL;
                int n  = s >> 2;
                int kq = (s & 3) << 2;
                cbs[(kq+0)*256 + n] = t[i].x;
                cbs[(kq+1)*256 + n] = t[i].y;
                cbs[(kq+2)*256 + n] = t[i].z;
                cbs[(kq+3)*256 + n] = t[i].w;
            }
            __syncthreads();
            #pragma unroll
            for (int k = 0; k < 16; k++) {
                float aa[4];
                #pragma unroll
                for (int i = 0; i < 4; i++) aa[i] = zs[(m0 + i) * D_N + k0 + k];
                float4 b0 = *(const float4*)&cbs[k * 256 + tx * 8];
                float4 b1 = *(const float4*)&cbs[k * 256 + tx * 8 + 4];
                float bb[8] = {b0.x, b0.y, b0.z, b0.w, b1.x, b1.y, b1.z, b1.w};
                #pragma unroll
                for (int i = 0; i < 4; i++)
                    #pragma unroll
                    for (int j = 0; j < 8; j++) acc[i][j] = fmaf(aa[i], bb[j], acc[i][j]);
            }
        }
        #pragma unroll
        for (int i = 0; i < 4; i++) {
            float4 o0 = make_float4(acc[i][0], acc[i][1], acc[i][2], acc[i][3]);
            float4 o1 = make_float4(acc[i][4], acc[i][5], acc[i][6], acc[i][7]);
            *(float4*)&S[(m0 + i) * K_N + nb + tx * 8]     = o0;
            *(float4*)&S[(m0 + i) * K_N + nb + tx * 8 + 4] = o1;
        }
    }
    __syncthreads();

    // ---- stage csq into smem ----
    for (int i = tid; i < K_N; i += TBL) cbs[i] = csq[i];
    __syncthreads();

    // ============================ Softmax ============================
    // logit = (2*dot - c_sq)/tau  (z_sq shift cancels in softmax)
    #pragma unroll
    for (int r = 0; r < 4; r++) {
        float* row = &S[(m0 + r) * K_N];
        float lg[32];
        float mx = -3.402823e38f;
        #pragma unroll
        for (int i = 0; i < 32; i++) {
            int n = tx + (i << 5);
            float v = fmaf(2.0f, row[n], -cbs[n]) * inv_tau;
            lg[i] = v;
            mx = fmaxf(mx, v);
        }
        #pragma unroll
        for (int o = 16; o; o >>= 1) mx = fmaxf(mx, __shfl_xor_sync(0xffffffffu, mx, o));
        float sum = 0.f;
        #pragma unroll
        for (int i = 0; i < 32; i++) { float e = __expf(lg[i] - mx); lg[i] = e; sum += e; }
        #pragma unroll
        for (int o = 16; o; o >>= 1) sum += __shfl_xor_sync(0xffffffffu, sum, o);
        float is = 1.0f / sum;
        float* prow = &out_p[(size_t)(bm0 + m0 + r) * K_N];
        #pragma unroll
        for (int i = 0; i < 32; i++) {
            int n = tx + (i << 5);
            float p = lg[i] * is;
            row[n]  = p;       // keep p in smem for stage B
            prow[n] = p;       // output
        }
    }
    __syncthreads();

    // ============================ Stage B ============================
    for (int db = 0; db < 2; db++) {
        int d0 = db * 256;
        float acc[4][8];
        #pragma unroll
        for (int i = 0; i < 4; i++)
            #pragma unroll
            for (int j = 0; j < 8; j++) acc[i][j] = 0.f;

        for (int nc = 0; nc < K_N; nc += 16) {
            float4 t[4];
            #pragma unroll
            for (int i = 0; i < 4; i++) {
                int s  = tid + i * TBL;
                int n  = s >> 6;             // 0..15
                int dq = (s & 63) << 2;      // 0..252
                t[i] = *(const float4*)&cb[(size_t)(nc + n) * D_N + d0 + dq];
            }
            __syncthreads();
            #pragma unroll
            for (int i = 0; i < 4; i++) {
                int s  = tid + i * TBL;
                int n  = s >> 6;
                int dq = (s & 63) << 2;
                *(float4*)&cbs[n * 256 + dq] = t[i];
            }
            __syncthreads();
            #pragma unroll
            for (int n = 0; n < 16; n++) {
                float aa[4];
                #pragma unroll
                for (int i = 0; i < 4; i++) aa[i] = S[(m0 + i) * K_N + nc + n];
                float4 b0 = *(const float4*)&cbs[n * 256 + tx * 8];
                float4 b1 = *(const float4*)&cbs[n * 256 + tx * 8 + 4];
                float bb[8] = {b0.x, b0.y, b0.z, b0.w, b1.x, b1.y, b1.z, b1.w};
                #pragma unroll
                for (int i = 0; i < 4; i++)
                    #pragma unroll
                    for (int j = 0; j < 8; j++) acc[i][j] = fmaf(aa[i], bb[j], acc[i][j]);
            }
        }
        // epilogue: write z_soft, update residual in-place
        #pragma unroll
        for (int i = 0; i < 4; i++) {
            size_t m = (size_t)(bm0 + m0 + i);
            #pragma unroll
            for (int h = 0; h < 2; h++) {
                int d = d0 + tx * 8 + h * 4;
                float4 o = make_float4(acc[i][h*4+0], acc[i][h*4+1], acc[i][h*4+2], acc[i][h*4+3]);
                float4 r = *(const float4*)&zs[(m0 + i) * D_N + d];
                *(float4*)&out_z[m * D_N + d] = o;
                float4 nr = make_float4(r.x - o.x, r.y - o.y, r.z - o.z, r.w - o.w);
                *(float4*)&g_zr[m * D_N + d] = nr;
            }
        }
    }
}

// ---------------------------------------------------------------------------
// kernel_launch: csq -> whiten -> 4 sequential fused level kernels
// Output layout: [ z_soft_levels (L*B*D) | p_levels (L*B*K) ] fp32
// ---------------------------------------------------------------------------
extern "C" void kernel_launch(void* const* d_in, const int* in_sizes, int n_in,
                              void* d_out, int out_size)
{
    const float* z0   = (const float*)d_in[0];
    const float* tau  = (const float*)d_in[1];
    const float* W    = (const float*)d_in[2];
    const float* cbks = (const float*)d_in[3];
    float* out   = (float*)d_out;
    float* out_z = out;
    float* out_p = out + (size_t)L_N * B_N * D_N;

    cudaFuncSetAttribute(level_kernel, cudaFuncAttributeMaxDynamicSharedMemorySize,
                         (int)SMEM_BYTES);

    csq_kernel<<<(L_N * K_N) / 8, 256>>>(cbks);
    whiten_kernel<<<dim3(D_N / 64, B_N / 64), 256>>>(z0, W);
    for (int l = 0; l < L_N; l++) {
        level_kernel<<<B_N / BM, TBL, SMEM_BYTES>>>(
            cbks + (size_t)l * K_N * D_N, l, tau,
            out_z + (size_t)l * B_N * D_N,
            out_p + (size_t)l * B_N * K_N);
    }
}